// round 1
// baseline (speedup 1.0000x reference)
#include <cuda_runtime.h>
#include <math.h>

#define BB 4
#define NN 8192
#define KNB 9
#define CH 7
#define BNK (BB*NN*KNB)
#define TILE 1024
#define BN_EPS 1e-5f

// scratch (allocation-free): SoA feature buffer [channel][bnk] and BN accumulators
__device__ float g_feat[CH * BNK];
__device__ float g_acc[28];   // [0:7) sum1, [7:14) sumsq1, [14:21) sum2, [21:28) sumsq2

__global__ void k_zero() {
    int t = threadIdx.x;
    if (t < 28) g_acc[t] = 0.f;
}

// ---------------------------------------------------------------------------
// K1: brute-force KNN (top-10 by dist = 2*x.y - |x|^2 - |y|^2, desc, ties->low idx)
//     + umbrella geometry + first 7x7 linear, accumulate BN1 stats
// ---------------------------------------------------------------------------
__global__ __launch_bounds__(256) void k_knn(const float* __restrict__ x,
                                             const float* __restrict__ w1) {
    __shared__ float4 tile[TILE];
    __shared__ float s_w1[49];
    __shared__ float s_acc[14];

    const int tid = threadIdx.x;
    const int blocksPerBatch = NN / 256;           // 32
    const int b = blockIdx.x / blocksPerBatch;
    const int n = (blockIdx.x % blocksPerBatch) * 256 + tid;
    const float* xb = x + (size_t)b * NN * 3;

    if (tid < 49) s_w1[tid] = w1[tid];
    if (tid < 14) s_acc[tid] = 0.f;

    const float x0 = xb[n*3+0], x1 = xb[n*3+1], x2 = xb[n*3+2];
    const float xsqi = fmaf(x2, x2, fmaf(x1, x1, x0*x0));

    float dst[10]; int idx[10];
#pragma unroll
    for (int k = 0; k < 10; k++) { dst[k] = -3.4e38f; idx[k] = -1; }

    for (int base = 0; base < NN; base += TILE) {
        __syncthreads();
        for (int j = tid; j < TILE; j += 256) {
            float a = xb[(base+j)*3+0];
            float c1 = xb[(base+j)*3+1];
            float c2 = xb[(base+j)*3+2];
            tile[j] = make_float4(a, c1, c2, fmaf(c2, c2, fmaf(c1, c1, a*a)));
        }
        __syncthreads();
#pragma unroll 4
        for (int j = 0; j < TILE; j++) {
            float4 s = tile[j];
            float xx = fmaf(x2, s.z, fmaf(x1, s.y, x0*s.x));
            float d  = fmaf(2.0f, xx, -xsqi) - s.w;   // matches ref rounding (2*xx exact)
            if (d > dst[9]) {
                int jj = base + j;
#pragma unroll
                for (int k = 0; k < 10; k++) {
                    if (d > dst[k]) {          // strict > keeps lower index on ties
                        float td = dst[k]; dst[k] = d;  d = td;
                        int   ti = idx[k]; idx[k] = jj; jj = ti;
                    }
                }
            }
        }
    }

    // --- umbrella geometry on the 9 non-self neighbors (idx[1..9]) ---
    float vx[9], vy[9], vz[9], ph[9];
#pragma unroll
    for (int k = 0; k < 9; k++) {
        int j = idx[k+1];
        float ax = xb[j*3+0] - x0;
        float ay = xb[j*3+1] - x1;
        float az = xb[j*3+2] - x2;
        vx[k] = ax; vy[k] = ay; vz[k] = az;
        ph[k] = atan2f(ay, ax);   // monotone in reference phi -> same argsort order
    }
    // unrolled bubble sort by phi (static indices -> registers)
#pragma unroll
    for (int a = 0; a < 8; a++) {
#pragma unroll
        for (int c = 0; c < 8 - a; c++) {
            if (ph[c] > ph[c+1]) {
                float t;
                t = ph[c]; ph[c] = ph[c+1]; ph[c+1] = t;
                t = vx[c]; vx[c] = vx[c+1]; vx[c+1] = t;
                t = vy[c]; vy[c] = vy[c+1]; vy[c+1] = t;
                t = vz[c]; vz[c] = vz[c+1]; vz[c+1] = t;
            }
        }
    }
    // sign mask from normal[0].x (sign unchanged by positive normalization)
    float c0x = vy[0]*vz[1] - vz[0]*vy[1] + 1e-5f;
    const float mask = (c0x > 0.f) ? 1.f : -1.f;

    float lsum[7], lsq[7];
#pragma unroll
    for (int o = 0; o < 7; o++) { lsum[o] = 0.f; lsq[o] = 0.f; }

    const int bnkBase = (b * NN + n) * KNB;
#pragma unroll
    for (int k = 0; k < 9; k++) {
        const int k2 = (k + 1 == 9) ? 0 : k + 1;
        float ax = vx[k],  ay = vy[k],  az = vz[k];
        float bx = vx[k2], by = vy[k2], bz = vz[k2];
        float cx = 0.5f*(ax+bx), cy = 0.5f*(ay+by), cz = 0.5f*(az+bz);
        float ux = ay*bz - az*by + 1e-5f;
        float uy = az*bx - ax*bz + 1e-5f;
        float uz = ax*by - ay*bx + 1e-5f;
        float inv = rsqrtf(ux*ux + uy*uy + uz*uz) * mask;
        ux *= inv; uy *= inv; uz *= inv;
        float pos = (cx*ux + cy*uy + cz*uz) * 0.57735026918962576f;  // /sqrt(3)
        float f[7] = {cx, cy, cz, ux, uy, uz, pos};
#pragma unroll
        for (int o = 0; o < 7; o++) {
            float h = 0.f;
#pragma unroll
            for (int c = 0; c < 7; c++) h = fmaf(f[c], s_w1[o*7+c], h);
            g_feat[o*BNK + bnkBase + k] = h;
            lsum[o] += h;
            lsq[o]   = fmaf(h, h, lsq[o]);
        }
    }

    // warp-shuffle reduce, then shared atomics, then global atomics
    const int lane = tid & 31;
#pragma unroll
    for (int o = 0; o < 7; o++) {
        float s = lsum[o], q = lsq[o];
        for (int off = 16; off; off >>= 1) {
            s += __shfl_xor_sync(0xffffffffu, s, off);
            q += __shfl_xor_sync(0xffffffffu, q, off);
        }
        if (lane == 0) { atomicAdd(&s_acc[o], s); atomicAdd(&s_acc[7+o], q); }
    }
    __syncthreads();
    if (tid < 14) atomicAdd(&g_acc[tid], s_acc[tid]);
}

// ---------------------------------------------------------------------------
// K2: BN1 + relu + linear2(+bias2), accumulate BN2 stats (in-place on g_feat)
// ---------------------------------------------------------------------------
__global__ __launch_bounds__(256) void k_mlp2(const float* __restrict__ gamma1,
                                              const float* __restrict__ beta1,
                                              const float* __restrict__ w2,
                                              const float* __restrict__ bias2) {
    __shared__ float s_w2[49], s_b2[7], s_scale[7], s_shift[7], s_acc[14];
    const int tid = threadIdx.x;
    if (tid < 49) s_w2[tid] = w2[tid];
    if (tid < 7) {
        s_b2[tid] = bias2[tid];
        float m = g_acc[tid] * (1.f / BNK);
        float v = g_acc[7+tid] * (1.f / BNK) - m*m;
        float sc = gamma1[tid] * rsqrtf(v + BN_EPS);
        s_scale[tid] = sc;
        s_shift[tid] = beta1[tid] - m*sc;
    }
    if (tid < 14) s_acc[tid] = 0.f;
    __syncthreads();

    const int bnk = blockIdx.x * 256 + tid;
    float r[7];
#pragma unroll
    for (int c = 0; c < 7; c++) {
        float h = g_feat[c*BNK + bnk];
        h = fmaf(h, s_scale[c], s_shift[c]);
        r[c] = fmaxf(h, 0.f);
    }
    float lsum[7], lsq[7];
#pragma unroll
    for (int o = 0; o < 7; o++) {
        float h = s_b2[o];
#pragma unroll
        for (int c = 0; c < 7; c++) h = fmaf(r[c], s_w2[o*7+c], h);
        g_feat[o*BNK + bnk] = h;
        lsum[o] = h;
        lsq[o]  = h*h;
    }
    const int lane = tid & 31;
#pragma unroll
    for (int o = 0; o < 7; o++) {
        float s = lsum[o], q = lsq[o];
        for (int off = 16; off; off >>= 1) {
            s += __shfl_xor_sync(0xffffffffu, s, off);
            q += __shfl_xor_sync(0xffffffffu, q, off);
        }
        if (lane == 0) { atomicAdd(&s_acc[o], s); atomicAdd(&s_acc[7+o], q); }
    }
    __syncthreads();
    if (tid < 14) atomicAdd(&g_acc[14+tid], s_acc[tid]);
}

// ---------------------------------------------------------------------------
// K3: BN2 + relu + linear3(+bias3) + maxpool over K, concat with x -> out
// ---------------------------------------------------------------------------
__global__ __launch_bounds__(256) void k_mlp3(const float* __restrict__ x,
                                              const float* __restrict__ gamma2,
                                              const float* __restrict__ beta2,
                                              const float* __restrict__ w3,
                                              const float* __restrict__ bias3,
                                              float* __restrict__ out) {
    __shared__ float s_w3[49], s_b3[7], s_scale[7], s_shift[7];
    const int tid = threadIdx.x;
    if (tid < 49) s_w3[tid] = w3[tid];
    if (tid < 7) {
        s_b3[tid] = bias3[tid];
        float m = g_acc[14+tid] * (1.f / BNK);
        float v = g_acc[21+tid] * (1.f / BNK) - m*m;
        float sc = gamma2[tid] * rsqrtf(v + BN_EPS);
        s_scale[tid] = sc;
        s_shift[tid] = beta2[tid] - m*sc;
    }
    __syncthreads();

    const int bn = blockIdx.x * 256 + tid;   // 0 .. B*N-1
    float best[7];
#pragma unroll
    for (int o = 0; o < 7; o++) best[o] = -3.4e38f;

#pragma unroll
    for (int k = 0; k < 9; k++) {
        float r[7];
#pragma unroll
        for (int c = 0; c < 7; c++) {
            float h = g_feat[c*BNK + bn*KNB + k];
            h = fmaf(h, s_scale[c], s_shift[c]);
            r[c] = fmaxf(h, 0.f);
        }
#pragma unroll
        for (int o = 0; o < 7; o++) {
            float h = s_b3[o];
#pragma unroll
            for (int c = 0; c < 7; c++) h = fmaf(r[c], s_w3[o*7+c], h);
            best[o] = fmaxf(best[o], h);
        }
    }
    out[bn*10+0] = x[bn*3+0];
    out[bn*10+1] = x[bn*3+1];
    out[bn*10+2] = x[bn*3+2];
#pragma unroll
    for (int o = 0; o < 7; o++) out[bn*10+3+o] = best[o];
}

extern "C" void kernel_launch(void* const* d_in, const int* in_sizes, int n_in,
                              void* d_out, int out_size) {
    const float* x      = (const float*)d_in[0];
    const float* w1     = (const float*)d_in[1];
    const float* gamma1 = (const float*)d_in[2];
    const float* beta1  = (const float*)d_in[3];
    const float* w2     = (const float*)d_in[4];
    const float* bias2  = (const float*)d_in[5];
    const float* gamma2 = (const float*)d_in[6];
    const float* beta2  = (const float*)d_in[7];
    const float* w3     = (const float*)d_in[8];
    const float* bias3  = (const float*)d_in[9];
    float* out = (float*)d_out;

    k_zero<<<1, 32>>>();
    k_knn<<<BB * (NN / 256), 256>>>(x, w1);
    k_mlp2<<<BNK / 256, 256>>>(gamma1, beta1, w2, bias2);
    k_mlp3<<<(BB * NN) / 256, 256>>>(x, gamma2, beta2, w3, bias3, out);
}